// round 13
// baseline (speedup 1.0000x reference)
#include <cuda_runtime.h>
#include <cuda_fp16.h>
#include <cstdint>
#include <math.h>

// Problem constants
#define BB 2
#define SS 128
#define DD 256
#define NH 8
#define HD 32
#define MTOT (BB*SS*SS)      // 32768 rows
#define QKVN 768
#define SCALE 0.17677669529663687f

// Scratch (allocation-free rule: __device__ globals)
__device__ __half g_x[MTOT * DD];
__device__ __half g_qkv[MTOT * QKVN];
__device__ __half g_att[MTOT * DD];
__device__ __half g_wq[QKVN * DD];
__device__ __half g_wo[DD * DD];
__device__ unsigned char g_mask[32768];

// ===========================================================================
// Helpers
// ===========================================================================
__device__ __forceinline__ uint32_t smem_u32(const void* p) {
    uint32_t a;
    asm("{ .reg .u64 t; cvta.to.shared.u64 t, %1; cvt.u32.u64 %0, t; }" : "=r"(a) : "l"(p));
    return a;
}
__device__ __forceinline__ uint32_t swz(uint32_t o) {       // SW128 swizzle
    return o ^ ((o >> 3) & 0x70);
}
__device__ __forceinline__ uint32_t packh2(float a, float b) {
    __half2 t = __floats2half2_rn(a, b);
    return *(uint32_t*)&t;
}
__device__ __forceinline__ void mma16816(float* c, const uint32_t* a, const uint32_t* b) {
    asm volatile("mma.sync.aligned.m16n8k16.row.col.f32.f16.f16.f32 "
        "{%0,%1,%2,%3}, {%4,%5,%6,%7}, {%8,%9}, {%0,%1,%2,%3};"
        : "+f"(c[0]), "+f"(c[1]), "+f"(c[2]), "+f"(c[3])
        : "r"(a[0]), "r"(a[1]), "r"(a[2]), "r"(a[3]), "r"(b[0]), "r"(b[1]));
}
#define LDSM_X4(r, addr) \
    asm volatile("ldmatrix.sync.aligned.m8n8.x4.shared.b16 {%0,%1,%2,%3}, [%4];" \
        : "=r"((r)[0]), "=r"((r)[1]), "=r"((r)[2]), "=r"((r)[3]) : "r"(addr))
#define LDSM_X4_T(r, addr) \
    asm volatile("ldmatrix.sync.aligned.m8n8.x4.trans.shared.b16 {%0,%1,%2,%3}, [%4];" \
        : "=r"((r)[0]), "=r"((r)[1]), "=r"((r)[2]), "=r"((r)[3]) : "r"(addr))
__device__ __forceinline__ void cpa16(uint32_t s, const void* g) {
    asm volatile("cp.async.cg.shared.global [%0], [%1], 16;" :: "r"(s), "l"(g));
}
#define CPA_COMMIT() asm volatile("cp.async.commit_group;" ::: "memory")
#define CPA_WAIT0() asm volatile("cp.async.wait_group 0;" ::: "memory")
#define CPA_WAIT1() asm volatile("cp.async.wait_group 1;" ::: "memory")

// ===========================================================================
// Prep: weight fp32->fp16 (blocks 0..1023) + mask sniff/normalize (1024..1151)
// ===========================================================================
__global__ __launch_bounds__(256)
void prep_kernel(const float* __restrict__ wq, const float* __restrict__ wo,
                 const unsigned char* __restrict__ m,
                 __half* __restrict__ oq, __half* __restrict__ oo)
{
    int bid = blockIdx.x;
    if (bid < 1024) {
        int i = bid * 256 + threadIdx.x;        // 0 .. 262143
        if (i < QKVN * DD) {
            oq[i] = __float2half_rn(wq[i]);
        } else {
            int j = i - QKVN * DD;
            oo[j] = __float2half_rn(wo[j]);
        }
    } else {
        // mask dtype sniff (redundant per block, cheap) + normalize.
        // uint8 mask: nonzero bytes at off%4==1; int32 0/1: only %4==0;
        // float32 0/1 (00 00 80 3f): only %4 in {2,3}.
        __shared__ int fa, fb;
        if (threadIdx.x == 0) { fa = 0; fb = 0; }
        __syncthreads();
        for (int i = threadIdx.x * 4; i < 32768; i += 256 * 4) {
            uint32_t w = *(const uint32_t*)(m + i);
            if (w) {
                if (w & 0x0000ff00u) fa = 1;
                if (w & 0x000000ffu) fb = 1;
            }
        }
        __syncthreads();
        int kind = fa ? 0 : (fb ? 1 : 2);
        int i = (bid - 1024) * 256 + threadIdx.x;
        unsigned char v;
        if (kind == 0)      v = m[i] ? 1 : 0;
        else if (kind == 1) v = ((const int*)m)[i] ? 1 : 0;
        else                v = (((const float*)m)[i] != 0.f) ? 1 : 0;
        g_mask[i] = v;
    }
}

// ===========================================================================
// LayerNorm: warp per row (8 rows/block), pure shfl reduction, fp16 out
// ===========================================================================
__global__ __launch_bounds__(256)
void ln_kernel(const float* __restrict__ in,
               const float* __restrict__ gamma,
               const float* __restrict__ beta,
               __half* __restrict__ o)
{
    int warp = threadIdx.x >> 5, lane = threadIdx.x & 31;
    int row = blockIdx.x * 8 + warp;
    const float* p = in + (size_t)row * DD + lane * 8;
    float4 a = *(const float4*)p;
    float4 b = *(const float4*)(p + 4);
    float s  = a.x + a.y + a.z + a.w + b.x + b.y + b.z + b.w;
    float s2 = a.x*a.x + a.y*a.y + a.z*a.z + a.w*a.w
             + b.x*b.x + b.y*b.y + b.z*b.z + b.w*b.w;
    #pragma unroll
    for (int of = 16; of > 0; of >>= 1) {
        s  += __shfl_xor_sync(0xffffffffu, s,  of);
        s2 += __shfl_xor_sync(0xffffffffu, s2, of);
    }
    float mu  = s * (1.f / 256.f);
    float var = s2 * (1.f / 256.f) - mu * mu;
    float r   = rsqrtf(var + 1e-5f);
    float4 g0 = *(const float4*)(gamma + lane * 8);
    float4 g1 = *(const float4*)(gamma + lane * 8 + 4);
    float4 t0 = *(const float4*)(beta + lane * 8);
    float4 t1 = *(const float4*)(beta + lane * 8 + 4);
    uint4 outv;
    outv.x = packh2((a.x - mu) * r * g0.x + t0.x, (a.y - mu) * r * g0.y + t0.y);
    outv.y = packh2((a.z - mu) * r * g0.z + t0.z, (a.w - mu) * r * g0.w + t0.w);
    outv.z = packh2((b.x - mu) * r * g1.x + t1.x, (b.y - mu) * r * g1.y + t1.y);
    outv.w = packh2((b.z - mu) * r * g1.z + t1.z, (b.w - mu) * r * g1.w + t1.w);
    *(uint4*)(o + (size_t)row * DD + lane * 8) = outv;
}

// ===========================================================================
// fp16 single-pass NT GEMM via mma.sync, cp.async double-buffered.
// BM=128, BN=128, BK=64; 256 threads = warps 4(m) x 2(n); warp tile 32x64.
// __launch_bounds__(256, 2): cap regs at 128 so 2 blocks/SM (16 warps).
// MODE 0: fp32 output. MODE 1 (QKV): fused rotary + q-scale, fp16 output.
// ===========================================================================
#define OFF_A 0
#define OFF_B 16384
#define STAGE_SZ 32768
#define GEMM_SMEM (2*STAGE_SZ + 1024)

template<int N, int MODE>
__global__ void __launch_bounds__(256, 2)
gemm_fp16_kernel(const __half* __restrict__ A,
                 const __half* __restrict__ B,
                 float* __restrict__ C,
                 __half* __restrict__ Ch)
{
    extern __shared__ char smem_raw[];
    char* smem = (char*)(((uintptr_t)smem_raw + 1023) & ~(uintptr_t)1023);
    uint32_t sb = smem_u32(smem);

    const int tid = threadIdx.x;
    const int lane = tid & 31;
    const int wid = tid >> 5;
    const int wm = wid & 3;
    const int wn = wid >> 2;
    const int m0 = blockIdx.y * 128;
    const int n0 = blockIdx.x * 128;

    float acc[2][8][4];
    #pragma unroll
    for (int i = 0; i < 2; i++)
        #pragma unroll
        for (int j = 0; j < 8; j++)
            #pragma unroll
            for (int k = 0; k < 4; k++) acc[i][j][k] = 0.f;

    const int aRow = (lane & 15);
    const int aHalf = (lane >> 4) * 16;
    const int bRow = ((lane >> 4) << 3) + (lane & 7);
    const int bHalf = ((lane >> 3) & 1) * 16;

    const int ldRow = tid >> 3;
    const int ldCs  = tid & 7;

    auto load_chunk = [&](int chunk, int buf) {
        int k0 = chunk * 64;
        uint32_t stage = sb + (uint32_t)buf * STAGE_SZ;
        #pragma unroll
        for (int s = 0; s < 4; s++) {
            int row = s * 32 + ldRow;
            uint32_t so = swz((uint32_t)(row * 128 + ldCs * 16));
            cpa16(stage + OFF_A + so, A + (size_t)(m0 + row) * 256 + k0 + ldCs * 8);
            cpa16(stage + OFF_B + so, B + (size_t)(n0 + row) * 256 + k0 + ldCs * 8);
        }
        CPA_COMMIT();
    };

    load_chunk(0, 0);

    for (int chunk = 0; chunk < 4; chunk++) {
        if (chunk < 3) {
            load_chunk(chunk + 1, (chunk + 1) & 1);
            CPA_WAIT1();
        } else {
            CPA_WAIT0();
        }
        __syncthreads();

        uint32_t stage = sb + (uint32_t)(chunk & 1) * STAGE_SZ;
        #pragma unroll
        for (int kk = 0; kk < 4; kk++) {
            int kb = kk * 32;
            uint32_t a[2][4];
            #pragma unroll
            for (int mt = 0; mt < 2; mt++) {
                uint32_t o = swz((uint32_t)((wm * 32 + mt * 16 + aRow) * 128 + kb + aHalf));
                LDSM_X4(a[mt], stage + OFF_A + o);
            }
            #pragma unroll
            for (int p = 0; p < 4; p++) {
                uint32_t bo = swz((uint32_t)((wn * 64 + p * 16 + bRow) * 128 + kb + bHalf));
                uint32_t bf[4];
                LDSM_X4(bf, stage + OFF_B + bo);
                #pragma unroll
                for (int t2 = 0; t2 < 2; t2++) {
                    int nt = p * 2 + t2;
                    #pragma unroll
                    for (int mt = 0; mt < 2; mt++)
                        mma16816(acc[mt][nt], a[mt], &bf[t2 * 2]);
                }
            }
        }
        __syncthreads();
    }

    #pragma unroll
    for (int mt = 0; mt < 2; mt++) {
        int row0 = m0 + wm * 32 + mt * 16 + (lane >> 2);
        #pragma unroll
        for (int nt = 0; nt < 8; nt++) {
            int colg = n0 + wn * 64 + nt * 8 + (lane & 3) * 2;
            float d0 = acc[mt][nt][0], d1 = acc[mt][nt][1];
            float d2 = acc[mt][nt][2], d3 = acc[mt][nt][3];
            if (MODE == 1) {
                // rotary on q head0 (cols 0..31) and k head0 (cols 256..287)
                if (colg < 32 || (colg >= 256 && colg < 288)) {
                    int p = (colg & 31) >> 1;
                    float invf = __expf(-(float)(p & 7) * 1.1512925464970228f);
                    #pragma unroll
                    for (int rr = 0; rr < 2; rr++) {
                        int m = row0 + rr * 8;
                        int xx = (m >> 7) & 127;
                        int yy = m & 127;
                        float pos  = (p < 8) ? (float)xx : (float)yy;
                        float tpos = (2.f * pos - 127.f) * (1.f / 127.f);
                        float sn, cs;
                        __sincosf(tpos * invf, &sn, &cs);
                        if (rr == 0) {
                            float e0 = d0, e1 = d1;
                            d0 = e0 * cs - e1 * sn;
                            d1 = e1 * cs + e0 * sn;
                        } else {
                            float e0 = d2, e1 = d3;
                            d2 = e0 * cs - e1 * sn;
                            d3 = e1 * cs + e0 * sn;
                        }
                    }
                }
                // scale q columns (scale commutes with rotation)
                if (colg < 256) {
                    d0 *= SCALE; d1 *= SCALE; d2 *= SCALE; d3 *= SCALE;
                }
                size_t b0 = (size_t)row0 * N + colg;
                size_t b1 = (size_t)(row0 + 8) * N + colg;
                *(uint32_t*)((char*)Ch + b0 * 2) = packh2(d0, d1);
                *(uint32_t*)((char*)Ch + b1 * 2) = packh2(d2, d3);
            } else {
                *(float2*)&C[(size_t)row0 * N + colg]       = make_float2(d0, d1);
                *(float2*)&C[(size_t)(row0 + 8) * N + colg] = make_float2(d2, d3);
            }
        }
    }
}

// ===========================================================================
// Tensorized attention, fp16, j-streamed in quarters to cut registers.
// One block per (h, x, b); 4 warps; warp owns 32 q-rows.
// No max-subtraction softmax => PV partial sums accumulate across quarters
// with no rescaling; divide by total sum once at the end.
// __launch_bounds__(128, 4): cap regs at 128 -> 4 blocks/SM (16 warps).
// ===========================================================================
#define AT_Q 0
#define AT_K 10240
#define AT_V 20480
#define AT_BIAS 30720
#define ATT_SMEM (31232 + 1024)

__global__ void __launch_bounds__(128, 4)
attn_kernel(const __half* __restrict__ qkv,
            __half* __restrict__ oh)
{
    extern __shared__ char smem_raw[];
    char* smem = (char*)(((uintptr_t)smem_raw + 1023) & ~(uintptr_t)1023);
    uint32_t sb = smem_u32(smem);

    const int hd  = blockIdx.x;
    const int xx  = blockIdx.y;
    const int b   = blockIdx.z;
    const int tid = threadIdx.x;
    const int lane = tid & 31;
    const int wm = tid >> 5;
    const int rowBase = b * (SS * SS) + xx * SS;

    // ---- Phase 1: vectorized staging (thread t = row t) ----
    {
        const char* ph = (const char*)(qkv + (size_t)(rowBase + tid) * QKVN + hd * HD);
        #pragma unroll
        for (int g = 0; g < 4; g++) {
            *(uint4*)(smem + AT_Q + tid * 80 + g * 16) = *(const uint4*)(ph + g * 16);
            *(uint4*)(smem + AT_K + tid * 80 + g * 16) = *(const uint4*)(ph + 512 + g * 16);
            *(uint4*)(smem + AT_V + tid * 80 + g * 16) = *(const uint4*)(ph + 1024 + g * 16);
        }
        *(float*)(smem + AT_BIAS + tid * 4) = g_mask[rowBase + tid] ? -1e9f : 0.f;
    }
    __syncthreads();

    const int aRow = (lane & 15);
    const int aHalf = (lane >> 4) * 16;
    const int bRow = ((lane >> 4) << 3) + (lane & 7);
    const int bHalf = ((lane >> 3) & 1) * 16;
    const int vjOff = ((lane >> 3) & 1) * 8 + (lane & 7);
    const int vdOff = ((lane >> 4) & 1) * 16;

    // Hoist Q fragments (16 regs): aq[kk][mt]
    uint32_t aq[2][2][4];
    #pragma unroll
    for (int kk = 0; kk < 2; kk++)
        #pragma unroll
        for (int mt = 0; mt < 2; mt++) {
            uint32_t o = (uint32_t)((wm * 32 + mt * 16 + aRow) * 80 + kk * 32 + aHalf);
            LDSM_X4(aq[kk][mt], sb + AT_Q + o);
        }

    float pacc[2][4][4];
    #pragma unroll
    for (int i = 0; i < 2; i++)
        #pragma unroll
        for (int j = 0; j < 4; j++)
            #pragma unroll
            for (int k = 0; k < 4; k++) pacc[i][j][k] = 0.f;
    float sum0[2] = {0.f, 0.f}, sum1[2] = {0.f, 0.f};

    // ---- Stream j in quarters of 32 keys ----
    #pragma unroll
    for (int jq = 0; jq < 4; jq++) {
        // S quarter: acc[mt][nt] over 4 n8-tiles (32 cols)
        float acc[2][4][4];
        #pragma unroll
        for (int i = 0; i < 2; i++)
            #pragma unroll
            for (int j = 0; j < 4; j++)
                #pragma unroll
                for (int k = 0; k < 4; k++) acc[i][j][k] = 0.f;

        #pragma unroll
        for (int kk = 0; kk < 2; kk++) {
            #pragma unroll
            for (int p = 0; p < 2; p++) {           // j tile of 16 within quarter
                uint32_t bo = (uint32_t)(((jq * 2 + p) * 16 + bRow) * 80 + kk * 32 + bHalf);
                uint32_t bf[4];
                LDSM_X4(bf, sb + AT_K + bo);
                #pragma unroll
                for (int t2 = 0; t2 < 2; t2++) {
                    int nt = p * 2 + t2;
                    #pragma unroll
                    for (int mt = 0; mt < 2; mt++)
                        mma16816(acc[mt][nt], aq[kk][mt], &bf[t2 * 2]);
                }
            }
        }

        // exp(+bias) -> P fragments for this quarter (2 k16 tiles)
        uint32_t P[2][2][4];
        #pragma unroll
        for (int mt = 0; mt < 2; mt++) {
            #pragma unroll
            for (int nt = 0; nt < 4; nt++) {
                float2 bb = *(float2*)(smem + AT_BIAS + (jq * 32 + nt * 8 + 2 * (lane & 3)) * 4);
                float e0 = __expf(acc[mt][nt][0] + bb.x);
                float e1 = __expf(acc[mt][nt][1] + bb.y);
                float e2 = __expf(acc[mt][nt][2] + bb.x);
                float e3 = __expf(acc[mt][nt][3] + bb.y);
                sum0[mt] += e0 + e1;
                sum1[mt] += e2 + e3;
                int ktp = nt >> 1, half = nt & 1;
                P[mt][ktp][half * 2 + 0] = packh2(e0, e1);
                P[mt][ktp][half * 2 + 1] = packh2(e2, e3);
            }
        }

        // PV for this quarter (2 k16 tiles of V)
        #pragma unroll
        for (int ktp = 0; ktp < 2; ktp++) {
            #pragma unroll
            for (int p2 = 0; p2 < 2; p2++) {
                uint32_t vo = (uint32_t)((jq * 32 + ktp * 16 + vjOff) * 80 + p2 * 32 + vdOff);
                uint32_t vf[4];
                LDSM_X4_T(vf, sb + AT_V + vo);
                #pragma unroll
                for (int t2 = 0; t2 < 2; t2++) {
                    int nt = p2 * 2 + t2;
                    #pragma unroll
                    for (int mt = 0; mt < 2; mt++)
                        mma16816(pacc[mt][nt], P[mt][ktp], &vf[t2 * 2]);
                }
            }
        }
    }

    // ---- Epilogue: reduce sums across quads, divide, fp16 store ----
    #pragma unroll
    for (int mt = 0; mt < 2; mt++) {
        float s0 = sum0[mt], s1 = sum1[mt];
        s0 += __shfl_xor_sync(0xffffffffu, s0, 1);
        s0 += __shfl_xor_sync(0xffffffffu, s0, 2);
        s1 += __shfl_xor_sync(0xffffffffu, s1, 1);
        s1 += __shfl_xor_sync(0xffffffffu, s1, 2);
        float r0 = 1.f / s0;
        float r1 = 1.f / s1;
        int row0 = rowBase + wm * 32 + mt * 16 + (lane >> 2);
        #pragma unroll
        for (int nt = 0; nt < 4; nt++) {
            int col = hd * HD + nt * 8 + 2 * (lane & 3);
            size_t base0 = (size_t)row0 * DD + col;
            size_t base1 = (size_t)(row0 + 8) * DD + col;
            *(uint32_t*)((char*)oh + base0 * 2) = packh2(pacc[mt][nt][0] * r0, pacc[mt][nt][1] * r0);
            *(uint32_t*)((char*)oh + base1 * 2) = packh2(pacc[mt][nt][2] * r1, pacc[mt][nt][3] * r1);
        }
    }
}

// ===========================================================================
extern "C" void kernel_launch(void* const* d_in, const int* in_sizes, int n_in,
                              void* d_out, int out_size)
{
    const float* pair_act = nullptr;
    const unsigned char* pair_mask = nullptr;
    const float* ln_gamma = nullptr;
    const float* ln_beta  = nullptr;
    const float* Wqkv = nullptr;
    const float* Wout = nullptr;

    for (int i = 0; i < n_in; i++) {
        int sz = in_sizes[i];
        if      (sz == 8388608) pair_act  = (const float*)d_in[i];
        else if (sz == 32768)   pair_mask = (const unsigned char*)d_in[i];
        else if (sz == 196608)  Wqkv      = (const float*)d_in[i];
        else if (sz == 65536)   Wout      = (const float*)d_in[i];
        else if (sz == 256) {
            if (!ln_gamma) ln_gamma = (const float*)d_in[i];
            else           ln_beta  = (const float*)d_in[i];
        }
    }

    float* out = (float*)d_out;

    void *px, *pq, *pat, *pwq, *pwo;
    cudaGetSymbolAddress(&px,  g_x);
    cudaGetSymbolAddress(&pq,  g_qkv);
    cudaGetSymbolAddress(&pat, g_att);
    cudaGetSymbolAddress(&pwq, g_wq);
    cudaGetSymbolAddress(&pwo, g_wo);

    cudaFuncSetAttribute(gemm_fp16_kernel<QKVN, 1>,
                         cudaFuncAttributeMaxDynamicSharedMemorySize, GEMM_SMEM);
    cudaFuncSetAttribute(gemm_fp16_kernel<DD, 0>,
                         cudaFuncAttributeMaxDynamicSharedMemorySize, GEMM_SMEM);
    cudaFuncSetAttribute(attn_kernel,
                         cudaFuncAttributeMaxDynamicSharedMemorySize, ATT_SMEM);

    // Launch order: 4th launch (index 3, the ncu capture target) = attn.
    prep_kernel<<<1152, 256>>>(Wqkv, Wout, pair_mask,
                               (__half*)pwq, (__half*)pwo);             // 0

    ln_kernel<<<MTOT / 8, 256>>>(pair_act, ln_gamma, ln_beta, (__half*)px);  // 1

    gemm_fp16_kernel<QKVN, 1><<<dim3(QKVN / 128, MTOT / 128), 256, GEMM_SMEM>>>(
        (const __half*)px, (const __half*)pwq, nullptr, (__half*)pq);   // 2

    attn_kernel<<<dim3(NH, SS, BB), 128, ATT_SMEM>>>(
        (const __half*)pq, (__half*)pat);                               // 3  <- profiled

    gemm_fp16_kernel<DD, 0><<<dim3(DD / 128, MTOT / 128), 256, GEMM_SMEM>>>(
        (const __half*)pat, (const __half*)pwo, out, nullptr);          // 4
}

// round 14
// speedup vs baseline: 1.4090x; 1.4090x over previous
#include <cuda_runtime.h>
#include <cuda_fp16.h>
#include <cstdint>
#include <math.h>

// Problem constants
#define BB 2
#define SS 128
#define DD 256
#define NH 8
#define HD 32
#define MTOT (BB*SS*SS)      // 32768 rows
#define QKVN 768
#define SCALE 0.17677669529663687f

// Scratch (allocation-free rule: __device__ globals)
__device__ __half g_x[MTOT * DD];
__device__ __half g_qkv[MTOT * QKVN];
__device__ __half g_att[MTOT * DD];
__device__ __half g_wq[QKVN * DD];
__device__ __half g_wo[DD * DD];
__device__ unsigned char g_mask[32768];

// ===========================================================================
// Helpers
// ===========================================================================
__device__ __forceinline__ uint32_t smem_u32(const void* p) {
    uint32_t a;
    asm("{ .reg .u64 t; cvta.to.shared.u64 t, %1; cvt.u32.u64 %0, t; }" : "=r"(a) : "l"(p));
    return a;
}
__device__ __forceinline__ uint32_t swz(uint32_t o) {       // SW128 swizzle
    return o ^ ((o >> 3) & 0x70);
}
__device__ __forceinline__ uint32_t packh2(float a, float b) {
    __half2 t = __floats2half2_rn(a, b);
    return *(uint32_t*)&t;
}
__device__ __forceinline__ void mma16816(float* c, const uint32_t* a, const uint32_t* b) {
    asm volatile("mma.sync.aligned.m16n8k16.row.col.f32.f16.f16.f32 "
        "{%0,%1,%2,%3}, {%4,%5,%6,%7}, {%8,%9}, {%0,%1,%2,%3};"
        : "+f"(c[0]), "+f"(c[1]), "+f"(c[2]), "+f"(c[3])
        : "r"(a[0]), "r"(a[1]), "r"(a[2]), "r"(a[3]), "r"(b[0]), "r"(b[1]));
}
#define LDSM_X4(r, addr) \
    asm volatile("ldmatrix.sync.aligned.m8n8.x4.shared.b16 {%0,%1,%2,%3}, [%4];" \
        : "=r"((r)[0]), "=r"((r)[1]), "=r"((r)[2]), "=r"((r)[3]) : "r"(addr))
#define LDSM_X4_T(r, addr) \
    asm volatile("ldmatrix.sync.aligned.m8n8.x4.trans.shared.b16 {%0,%1,%2,%3}, [%4];" \
        : "=r"((r)[0]), "=r"((r)[1]), "=r"((r)[2]), "=r"((r)[3]) : "r"(addr))
__device__ __forceinline__ void cpa16(uint32_t s, const void* g) {
    asm volatile("cp.async.cg.shared.global [%0], [%1], 16;" :: "r"(s), "l"(g));
}
#define CPA_COMMIT() asm volatile("cp.async.commit_group;" ::: "memory")
#define CPA_WAIT0() asm volatile("cp.async.wait_group 0;" ::: "memory")
#define CPA_WAIT1() asm volatile("cp.async.wait_group 1;" ::: "memory")

// ===========================================================================
// Prep: weight fp32->fp16 (blocks 0..1023) + mask sniff/normalize (1024..1151)
// ===========================================================================
__global__ __launch_bounds__(256)
void prep_kernel(const float* __restrict__ wq, const float* __restrict__ wo,
                 const unsigned char* __restrict__ m,
                 __half* __restrict__ oq, __half* __restrict__ oo)
{
    int bid = blockIdx.x;
    if (bid < 1024) {
        int i = bid * 256 + threadIdx.x;        // 0 .. 262143
        if (i < QKVN * DD) {
            oq[i] = __float2half_rn(wq[i]);
        } else {
            int j = i - QKVN * DD;
            oo[j] = __float2half_rn(wo[j]);
        }
    } else {
        // mask dtype sniff (redundant per block, cheap) + normalize.
        // uint8 mask: nonzero bytes at off%4==1; int32 0/1: only %4==0;
        // float32 0/1 (00 00 80 3f): only %4 in {2,3}.
        __shared__ int fa, fb;
        if (threadIdx.x == 0) { fa = 0; fb = 0; }
        __syncthreads();
        for (int i = threadIdx.x * 4; i < 32768; i += 256 * 4) {
            uint32_t w = *(const uint32_t*)(m + i);
            if (w) {
                if (w & 0x0000ff00u) fa = 1;
                if (w & 0x000000ffu) fb = 1;
            }
        }
        __syncthreads();
        int kind = fa ? 0 : (fb ? 1 : 2);
        int i = (bid - 1024) * 256 + threadIdx.x;
        unsigned char v;
        if (kind == 0)      v = m[i] ? 1 : 0;
        else if (kind == 1) v = ((const int*)m)[i] ? 1 : 0;
        else                v = (((const float*)m)[i] != 0.f) ? 1 : 0;
        g_mask[i] = v;
    }
}

// ===========================================================================
// LayerNorm: warp per row (8 rows/block), pure shfl reduction, fp16 out
// ===========================================================================
__global__ __launch_bounds__(256)
void ln_kernel(const float* __restrict__ in,
               const float* __restrict__ gamma,
               const float* __restrict__ beta,
               __half* __restrict__ o)
{
    int warp = threadIdx.x >> 5, lane = threadIdx.x & 31;
    int row = blockIdx.x * 8 + warp;
    const float* p = in + (size_t)row * DD + lane * 8;
    float4 a = *(const float4*)p;
    float4 b = *(const float4*)(p + 4);
    float s  = a.x + a.y + a.z + a.w + b.x + b.y + b.z + b.w;
    float s2 = a.x*a.x + a.y*a.y + a.z*a.z + a.w*a.w
             + b.x*b.x + b.y*b.y + b.z*b.z + b.w*b.w;
    #pragma unroll
    for (int of = 16; of > 0; of >>= 1) {
        s  += __shfl_xor_sync(0xffffffffu, s,  of);
        s2 += __shfl_xor_sync(0xffffffffu, s2, of);
    }
    float mu  = s * (1.f / 256.f);
    float var = s2 * (1.f / 256.f) - mu * mu;
    float r   = rsqrtf(var + 1e-5f);
    float4 g0 = *(const float4*)(gamma + lane * 8);
    float4 g1 = *(const float4*)(gamma + lane * 8 + 4);
    float4 t0 = *(const float4*)(beta + lane * 8);
    float4 t1 = *(const float4*)(beta + lane * 8 + 4);
    uint4 outv;
    outv.x = packh2((a.x - mu) * r * g0.x + t0.x, (a.y - mu) * r * g0.y + t0.y);
    outv.y = packh2((a.z - mu) * r * g0.z + t0.z, (a.w - mu) * r * g0.w + t0.w);
    outv.z = packh2((b.x - mu) * r * g1.x + t1.x, (b.y - mu) * r * g1.y + t1.y);
    outv.w = packh2((b.z - mu) * r * g1.z + t1.z, (b.w - mu) * r * g1.w + t1.w);
    *(uint4*)(o + (size_t)row * DD + lane * 8) = outv;
}

// ===========================================================================
// fp16 single-pass NT GEMM via mma.sync, cp.async double-buffered.
// BM=128, BN=128, BK=64; 256 threads = warps 4(m) x 2(n); warp tile 32x64.
// __launch_bounds__(256, 2): cap regs at 128 so 2 blocks/SM (16 warps).
// MODE 0: fp32 output. MODE 1 (QKV): fused rotary + q-scale, fp16 output.
// ===========================================================================
#define OFF_A 0
#define OFF_B 16384
#define STAGE_SZ 32768
#define GEMM_SMEM (2*STAGE_SZ + 1024)

template<int N, int MODE>
__global__ void __launch_bounds__(256, 2)
gemm_fp16_kernel(const __half* __restrict__ A,
                 const __half* __restrict__ B,
                 float* __restrict__ C,
                 __half* __restrict__ Ch)
{
    extern __shared__ char smem_raw[];
    char* smem = (char*)(((uintptr_t)smem_raw + 1023) & ~(uintptr_t)1023);
    uint32_t sb = smem_u32(smem);

    const int tid = threadIdx.x;
    const int lane = tid & 31;
    const int wid = tid >> 5;
    const int wm = wid & 3;
    const int wn = wid >> 2;
    const int m0 = blockIdx.y * 128;
    const int n0 = blockIdx.x * 128;

    float acc[2][8][4];
    #pragma unroll
    for (int i = 0; i < 2; i++)
        #pragma unroll
        for (int j = 0; j < 8; j++)
            #pragma unroll
            for (int k = 0; k < 4; k++) acc[i][j][k] = 0.f;

    const int aRow = (lane & 15);
    const int aHalf = (lane >> 4) * 16;
    const int bRow = ((lane >> 4) << 3) + (lane & 7);
    const int bHalf = ((lane >> 3) & 1) * 16;

    const int ldRow = tid >> 3;
    const int ldCs  = tid & 7;

    auto load_chunk = [&](int chunk, int buf) {
        int k0 = chunk * 64;
        uint32_t stage = sb + (uint32_t)buf * STAGE_SZ;
        #pragma unroll
        for (int s = 0; s < 4; s++) {
            int row = s * 32 + ldRow;
            uint32_t so = swz((uint32_t)(row * 128 + ldCs * 16));
            cpa16(stage + OFF_A + so, A + (size_t)(m0 + row) * 256 + k0 + ldCs * 8);
            cpa16(stage + OFF_B + so, B + (size_t)(n0 + row) * 256 + k0 + ldCs * 8);
        }
        CPA_COMMIT();
    };

    load_chunk(0, 0);

    for (int chunk = 0; chunk < 4; chunk++) {
        if (chunk < 3) {
            load_chunk(chunk + 1, (chunk + 1) & 1);
            CPA_WAIT1();
        } else {
            CPA_WAIT0();
        }
        __syncthreads();

        uint32_t stage = sb + (uint32_t)(chunk & 1) * STAGE_SZ;
        #pragma unroll
        for (int kk = 0; kk < 4; kk++) {
            int kb = kk * 32;
            uint32_t a[2][4];
            #pragma unroll
            for (int mt = 0; mt < 2; mt++) {
                uint32_t o = swz((uint32_t)((wm * 32 + mt * 16 + aRow) * 128 + kb + aHalf));
                LDSM_X4(a[mt], stage + OFF_A + o);
            }
            #pragma unroll
            for (int p = 0; p < 4; p++) {
                uint32_t bo = swz((uint32_t)((wn * 64 + p * 16 + bRow) * 128 + kb + bHalf));
                uint32_t bf[4];
                LDSM_X4(bf, stage + OFF_B + bo);
                #pragma unroll
                for (int t2 = 0; t2 < 2; t2++) {
                    int nt = p * 2 + t2;
                    #pragma unroll
                    for (int mt = 0; mt < 2; mt++)
                        mma16816(acc[mt][nt], a[mt], &bf[t2 * 2]);
                }
            }
        }
        __syncthreads();
    }

    #pragma unroll
    for (int mt = 0; mt < 2; mt++) {
        int row0 = m0 + wm * 32 + mt * 16 + (lane >> 2);
        #pragma unroll
        for (int nt = 0; nt < 8; nt++) {
            int colg = n0 + wn * 64 + nt * 8 + (lane & 3) * 2;
            float d0 = acc[mt][nt][0], d1 = acc[mt][nt][1];
            float d2 = acc[mt][nt][2], d3 = acc[mt][nt][3];
            if (MODE == 1) {
                // rotary on q head0 (cols 0..31) and k head0 (cols 256..287)
                if (colg < 32 || (colg >= 256 && colg < 288)) {
                    int p = (colg & 31) >> 1;
                    float invf = __expf(-(float)(p & 7) * 1.1512925464970228f);
                    #pragma unroll
                    for (int rr = 0; rr < 2; rr++) {
                        int m = row0 + rr * 8;
                        int xx = (m >> 7) & 127;
                        int yy = m & 127;
                        float pos  = (p < 8) ? (float)xx : (float)yy;
                        float tpos = (2.f * pos - 127.f) * (1.f / 127.f);
                        float sn, cs;
                        __sincosf(tpos * invf, &sn, &cs);
                        if (rr == 0) {
                            float e0 = d0, e1 = d1;
                            d0 = e0 * cs - e1 * sn;
                            d1 = e1 * cs + e0 * sn;
                        } else {
                            float e0 = d2, e1 = d3;
                            d2 = e0 * cs - e1 * sn;
                            d3 = e1 * cs + e0 * sn;
                        }
                    }
                }
                // scale q columns (scale commutes with rotation)
                if (colg < 256) {
                    d0 *= SCALE; d1 *= SCALE; d2 *= SCALE; d3 *= SCALE;
                }
                size_t b0 = (size_t)row0 * N + colg;
                size_t b1 = (size_t)(row0 + 8) * N + colg;
                *(uint32_t*)((char*)Ch + b0 * 2) = packh2(d0, d1);
                *(uint32_t*)((char*)Ch + b1 * 2) = packh2(d2, d3);
            } else {
                *(float2*)&C[(size_t)row0 * N + colg]       = make_float2(d0, d1);
                *(float2*)&C[(size_t)(row0 + 8) * N + colg] = make_float2(d2, d3);
            }
        }
    }
}

// ===========================================================================
// Tensorized attention, fp16 single-pass (R12 monolithic body).
// One block per (h, x, b); 4 warps; warp owns 32 q-rows.
// __launch_bounds__(128, 3): cap regs at 170 (natural demand ~180; small
// shave, no spills) -> 3 blocks/SM = 12 warps.
// Softmax without max-subtraction (scores O(1); masked -> exp(-1e9)=0).
// V row layout; PV uses ldmatrix.trans. smem rows padded to 80B.
// ===========================================================================
#define AT_Q 0
#define AT_K 10240
#define AT_V 20480
#define AT_BIAS 30720
#define ATT_SMEM (31232 + 1024)

__global__ void __launch_bounds__(128, 3)
attn_kernel(const __half* __restrict__ qkv,
            __half* __restrict__ oh)
{
    extern __shared__ char smem_raw[];
    char* smem = (char*)(((uintptr_t)smem_raw + 1023) & ~(uintptr_t)1023);
    uint32_t sb = smem_u32(smem);

    const int hd  = blockIdx.x;
    const int xx  = blockIdx.y;
    const int b   = blockIdx.z;
    const int tid = threadIdx.x;
    const int lane = tid & 31;
    const int wm = tid >> 5;
    const int rowBase = b * (SS * SS) + xx * SS;

    // ---- Phase 1: vectorized staging (thread t = row t) ----
    {
        const char* ph = (const char*)(qkv + (size_t)(rowBase + tid) * QKVN + hd * HD);
        #pragma unroll
        for (int g = 0; g < 4; g++) {
            *(uint4*)(smem + AT_Q + tid * 80 + g * 16) = *(const uint4*)(ph + g * 16);
            *(uint4*)(smem + AT_K + tid * 80 + g * 16) = *(const uint4*)(ph + 512 + g * 16);
            *(uint4*)(smem + AT_V + tid * 80 + g * 16) = *(const uint4*)(ph + 1024 + g * 16);
        }
        *(float*)(smem + AT_BIAS + tid * 4) = g_mask[rowBase + tid] ? -1e9f : 0.f;
    }
    __syncthreads();

    const int aRow = (lane & 15);
    const int aHalf = (lane >> 4) * 16;
    const int bRow = ((lane >> 4) << 3) + (lane & 7);
    const int bHalf = ((lane >> 3) & 1) * 16;

    // ---- Phase 2: S = Q K^T ----
    float acc[2][16][4];
    #pragma unroll
    for (int i = 0; i < 2; i++)
        #pragma unroll
        for (int j = 0; j < 16; j++)
            #pragma unroll
            for (int k = 0; k < 4; k++) acc[i][j][k] = 0.f;

    #pragma unroll
    for (int kk = 0; kk < 2; kk++) {
        uint32_t a[2][4];
        #pragma unroll
        for (int mt = 0; mt < 2; mt++) {
            uint32_t o = (uint32_t)((wm * 32 + mt * 16 + aRow) * 80 + kk * 32 + aHalf);
            LDSM_X4(a[mt], sb + AT_Q + o);
        }
        #pragma unroll
        for (int p = 0; p < 8; p++) {
            uint32_t bo = (uint32_t)((p * 16 + bRow) * 80 + kk * 32 + bHalf);
            uint32_t bf[4];
            LDSM_X4(bf, sb + AT_K + bo);
            #pragma unroll
            for (int t2 = 0; t2 < 2; t2++) {
                int nt = p * 2 + t2;
                #pragma unroll
                for (int mt = 0; mt < 2; mt++)
                    mma16816(acc[mt][nt], a[mt], &bf[t2 * 2]);
            }
        }
    }

    // ---- Phase 3: softmax (no max-sub) + P fp16 fragments ----
    uint32_t Ph[2][8][4];
    float rsum[2][2];

    #pragma unroll
    for (int mt = 0; mt < 2; mt++) {
        float s0 = 0.f, s1 = 0.f;
        #pragma unroll
        for (int nt = 0; nt < 16; nt++) {
            float2 bb = *(float2*)(smem + AT_BIAS + (nt * 8 + 2 * (lane & 3)) * 4);
            float e0 = __expf(acc[mt][nt][0] + bb.x);
            float e1 = __expf(acc[mt][nt][1] + bb.y);
            float e2 = __expf(acc[mt][nt][2] + bb.x);
            float e3 = __expf(acc[mt][nt][3] + bb.y);
            acc[mt][nt][0] = e0; acc[mt][nt][1] = e1;
            acc[mt][nt][2] = e2; acc[mt][nt][3] = e3;
            s0 += e0 + e1; s1 += e2 + e3;
        }
        s0 += __shfl_xor_sync(0xffffffffu, s0, 1);
        s0 += __shfl_xor_sync(0xffffffffu, s0, 2);
        s1 += __shfl_xor_sync(0xffffffffu, s1, 1);
        s1 += __shfl_xor_sync(0xffffffffu, s1, 2);
        rsum[mt][0] = s0; rsum[mt][1] = s1;

        #pragma unroll
        for (int kt = 0; kt < 8; kt++) {
            #pragma unroll
            for (int half = 0; half < 2; half++) {
                const float* c = acc[mt][2 * kt + half];
                Ph[mt][kt][half * 2 + 0] = packh2(c[0], c[1]);
                Ph[mt][kt][half * 2 + 1] = packh2(c[2], c[3]);
            }
        }
    }

    // ---- Phase 4: O = P V via ldmatrix.trans on row-layout V ----
    float pacc[2][4][4];
    #pragma unroll
    for (int i = 0; i < 2; i++)
        #pragma unroll
        for (int j = 0; j < 4; j++)
            #pragma unroll
            for (int k = 0; k < 4; k++) pacc[i][j][k] = 0.f;

    const int vjOff = ((lane >> 3) & 1) * 8 + (lane & 7);
    const int vdOff = ((lane >> 4) & 1) * 16;

    #pragma unroll
    for (int kt = 0; kt < 8; kt++) {
        #pragma unroll
        for (int p2 = 0; p2 < 2; p2++) {
            uint32_t vo = (uint32_t)((kt * 16 + vjOff) * 80 + p2 * 32 + vdOff);
            uint32_t vf[4];
            LDSM_X4_T(vf, sb + AT_V + vo);
            #pragma unroll
            for (int t2 = 0; t2 < 2; t2++) {
                int nt = p2 * 2 + t2;
                #pragma unroll
                for (int mt = 0; mt < 2; mt++)
                    mma16816(pacc[mt][nt], Ph[mt][kt], &vf[t2 * 2]);
            }
        }
    }

    // ---- Phase 5: epilogue (divide by row sum, fp16 store) ----
    #pragma unroll
    for (int mt = 0; mt < 2; mt++) {
        float r0 = 1.f / rsum[mt][0];
        float r1 = 1.f / rsum[mt][1];
        int row0 = rowBase + wm * 32 + mt * 16 + (lane >> 2);
        #pragma unroll
        for (int nt = 0; nt < 4; nt++) {
            int col = hd * HD + nt * 8 + 2 * (lane & 3);
            size_t base0 = (size_t)row0 * DD + col;
            size_t base1 = (size_t)(row0 + 8) * DD + col;
            *(uint32_t*)((char*)oh + base0 * 2) = packh2(pacc[mt][nt][0] * r0, pacc[mt][nt][1] * r0);
            *(uint32_t*)((char*)oh + base1 * 2) = packh2(pacc[mt][nt][2] * r1, pacc[mt][nt][3] * r1);
        }
    }
}

// ===========================================================================
extern "C" void kernel_launch(void* const* d_in, const int* in_sizes, int n_in,
                              void* d_out, int out_size)
{
    const float* pair_act = nullptr;
    const unsigned char* pair_mask = nullptr;
    const float* ln_gamma = nullptr;
    const float* ln_beta  = nullptr;
    const float* Wqkv = nullptr;
    const float* Wout = nullptr;

    for (int i = 0; i < n_in; i++) {
        int sz = in_sizes[i];
        if      (sz == 8388608) pair_act  = (const float*)d_in[i];
        else if (sz == 32768)   pair_mask = (const unsigned char*)d_in[i];
        else if (sz == 196608)  Wqkv      = (const float*)d_in[i];
        else if (sz == 65536)   Wout      = (const float*)d_in[i];
        else if (sz == 256) {
            if (!ln_gamma) ln_gamma = (const float*)d_in[i];
            else           ln_beta  = (const float*)d_in[i];
        }
    }

    float* out = (float*)d_out;

    void *px, *pq, *pat, *pwq, *pwo;
    cudaGetSymbolAddress(&px,  g_x);
    cudaGetSymbolAddress(&pq,  g_qkv);
    cudaGetSymbolAddress(&pat, g_att);
    cudaGetSymbolAddress(&pwq, g_wq);
    cudaGetSymbolAddress(&pwo, g_wo);

    cudaFuncSetAttribute(gemm_fp16_kernel<QKVN, 1>,
                         cudaFuncAttributeMaxDynamicSharedMemorySize, GEMM_SMEM);
    cudaFuncSetAttribute(gemm_fp16_kernel<DD, 0>,
                         cudaFuncAttributeMaxDynamicSharedMemorySize, GEMM_SMEM);
    cudaFuncSetAttribute(attn_kernel,
                         cudaFuncAttributeMaxDynamicSharedMemorySize, ATT_SMEM);

    // Launch order: 4th launch (index 3, the ncu capture target) = attn.
    prep_kernel<<<1152, 256>>>(Wqkv, Wout, pair_mask,
                               (__half*)pwq, (__half*)pwo);             // 0

    ln_kernel<<<MTOT / 8, 256>>>(pair_act, ln_gamma, ln_beta, (__half*)px);  // 1

    gemm_fp16_kernel<QKVN, 1><<<dim3(QKVN / 128, MTOT / 128), 256, GEMM_SMEM>>>(
        (const __half*)px, (const __half*)pwq, nullptr, (__half*)pq);   // 2

    attn_kernel<<<dim3(NH, SS, BB), 128, ATT_SMEM>>>(
        (const __half*)pq, (__half*)pat);                               // 3  <- profiled

    gemm_fp16_kernel<DD, 0><<<dim3(DD / 128, MTOT / 128), 256, GEMM_SMEM>>>(
        (const __half*)pat, (const __half*)pwo, out, nullptr);          // 4
}

// round 16
// speedup vs baseline: 1.7225x; 1.2225x over previous
#include <cuda_runtime.h>
#include <cuda_fp16.h>
#include <cstdint>
#include <math.h>

// Problem constants
#define BB 2
#define SS 128
#define DD 256
#define NH 8
#define HD 32
#define MTOT (BB*SS*SS)      // 32768 rows
#define QKVN 768
#define SCALE 0.17677669529663687f

// Scratch (allocation-free rule: __device__ globals)
__device__ __half g_x[MTOT * DD];
__device__ __half g_att[MTOT * DD];
__device__ __half g_wq[QKVN * DD];
__device__ __half g_wo[DD * DD];
__device__ unsigned char g_mask[32768];

// ===========================================================================
// Helpers
// ===========================================================================
__device__ __forceinline__ uint32_t smem_u32(const void* p) {
    uint32_t a;
    asm("{ .reg .u64 t; cvta.to.shared.u64 t, %1; cvt.u32.u64 %0, t; }" : "=r"(a) : "l"(p));
    return a;
}
__device__ __forceinline__ uint32_t swz(uint32_t o) {       // SW128 swizzle
    return o ^ ((o >> 3) & 0x70);
}
__device__ __forceinline__ uint32_t packh2(float a, float b) {
    __half2 t = __floats2half2_rn(a, b);
    return *(uint32_t*)&t;
}
__device__ __forceinline__ void mma16816(float* c, const uint32_t* a, const uint32_t* b) {
    asm volatile("mma.sync.aligned.m16n8k16.row.col.f32.f16.f16.f32 "
        "{%0,%1,%2,%3}, {%4,%5,%6,%7}, {%8,%9}, {%0,%1,%2,%3};"
        : "+f"(c[0]), "+f"(c[1]), "+f"(c[2]), "+f"(c[3])
        : "r"(a[0]), "r"(a[1]), "r"(a[2]), "r"(a[3]), "r"(b[0]), "r"(b[1]));
}
#define LDSM_X4(r, addr) \
    asm volatile("ldmatrix.sync.aligned.m8n8.x4.shared.b16 {%0,%1,%2,%3}, [%4];" \
        : "=r"((r)[0]), "=r"((r)[1]), "=r"((r)[2]), "=r"((r)[3]) : "r"(addr))
#define LDSM_X4_T(r, addr) \
    asm volatile("ldmatrix.sync.aligned.m8n8.x4.trans.shared.b16 {%0,%1,%2,%3}, [%4];" \
        : "=r"((r)[0]), "=r"((r)[1]), "=r"((r)[2]), "=r"((r)[3]) : "r"(addr))
__device__ __forceinline__ void cpa16(uint32_t s, const void* g) {
    asm volatile("cp.async.cg.shared.global [%0], [%1], 16;" :: "r"(s), "l"(g));
}
#define CPA_COMMIT() asm volatile("cp.async.commit_group;" ::: "memory")
#define CPA_WAIT0() asm volatile("cp.async.wait_group 0;" ::: "memory")
#define CPA_WAIT1() asm volatile("cp.async.wait_group 1;" ::: "memory")

// ===========================================================================
// Weight conversion (fp32 -> fp16), both matrices
// ===========================================================================
__global__ __launch_bounds__(256)
void convw_kernel(const float* __restrict__ wq, const float* __restrict__ wo,
                  __half* __restrict__ oq, __half* __restrict__ oo)
{
    int i = blockIdx.x * 256 + threadIdx.x;        // 0 .. 262143
    if (i < QKVN * DD) {
        oq[i] = __float2half_rn(wq[i]);
    } else {
        int j = i - QKVN * DD;
        oo[j] = __float2half_rn(wo[j]);
    }
}

// ===========================================================================
// Mask: fused dtype-sniff (per-block redundant scan) + normalize.
// ===========================================================================
__global__ __launch_bounds__(256)
void mask_kernel(const unsigned char* __restrict__ m)
{
    __shared__ int fa, fb;
    if (threadIdx.x == 0) { fa = 0; fb = 0; }
    __syncthreads();
    for (int i = threadIdx.x * 4; i < 32768; i += 256 * 4) {
        uint32_t w = *(const uint32_t*)(m + i);
        if (w) {
            if (w & 0x0000ff00u) fa = 1;
            if (w & 0x000000ffu) fb = 1;
        }
    }
    __syncthreads();
    int kind = fa ? 0 : (fb ? 1 : 2);
    int i = blockIdx.x * 256 + threadIdx.x;
    unsigned char v;
    if (kind == 0)      v = m[i] ? 1 : 0;
    else if (kind == 1) v = ((const int*)m)[i] ? 1 : 0;
    else                v = (((const float*)m)[i] != 0.f) ? 1 : 0;
    g_mask[i] = v;
}

// ===========================================================================
// LayerNorm: warp per row (8 rows/block), pure shfl reduction, fp16 out
// ===========================================================================
__global__ __launch_bounds__(256)
void ln_kernel(const float* __restrict__ in,
               const float* __restrict__ gamma,
               const float* __restrict__ beta,
               __half* __restrict__ o)
{
    int warp = threadIdx.x >> 5, lane = threadIdx.x & 31;
    int row = blockIdx.x * 8 + warp;
    const float* p = in + (size_t)row * DD + lane * 8;
    float4 a = *(const float4*)p;
    float4 b = *(const float4*)(p + 4);
    float s  = a.x + a.y + a.z + a.w + b.x + b.y + b.z + b.w;
    float s2 = a.x*a.x + a.y*a.y + a.z*a.z + a.w*a.w
             + b.x*b.x + b.y*b.y + b.z*b.z + b.w*b.w;
    #pragma unroll
    for (int of = 16; of > 0; of >>= 1) {
        s  += __shfl_xor_sync(0xffffffffu, s,  of);
        s2 += __shfl_xor_sync(0xffffffffu, s2, of);
    }
    float mu  = s * (1.f / 256.f);
    float var = s2 * (1.f / 256.f) - mu * mu;
    float r   = rsqrtf(var + 1e-5f);
    float4 g0 = *(const float4*)(gamma + lane * 8);
    float4 g1 = *(const float4*)(gamma + lane * 8 + 4);
    float4 t0 = *(const float4*)(beta + lane * 8);
    float4 t1 = *(const float4*)(beta + lane * 8 + 4);
    uint4 outv;
    outv.x = packh2((a.x - mu) * r * g0.x + t0.x, (a.y - mu) * r * g0.y + t0.y);
    outv.y = packh2((a.z - mu) * r * g0.z + t0.z, (a.w - mu) * r * g0.w + t0.w);
    outv.z = packh2((b.x - mu) * r * g1.x + t1.x, (b.y - mu) * r * g1.y + t1.y);
    outv.w = packh2((b.z - mu) * r * g1.z + t1.z, (b.w - mu) * r * g1.w + t1.w);
    *(uint4*)(o + (size_t)row * DD + lane * 8) = outv;
}

// ===========================================================================
// FUSED per-(head, stripe) QKV-GEMM + attention.
// Block = (head hd, stripe s): computes QKV[128 rows x 96 cols] for its head
// (K=256, cp.async 2-stage, 80B-pitch smem, BK=32), then attention:
//   - Q stays in registers (C-frag == A-frag identity), rotary+scale inline
//   - K/V C-frags stored to 80B-pitch smem, consumed by LDSM / LDSM_T
//   - softmax without max-sub; output fp16 to g_att
// 128 threads, 4 warps (warp owns 32 q-rows). __launch_bounds__(128,3).
// ===========================================================================
#define F_ASTAGE 0                         // 2 x 10240 (128 rows x 80B)
#define F_WSTAGE 20480                     // 2 x 7680  (96 rows x 80B)
#define F_K      35840                     // 10240
#define F_V      46080                     // 10240
#define F_BIAS   56320                     // 512
#define F_SMEM   (56832 + 1024)

__global__ void __launch_bounds__(128, 3)
fused_qkv_attn_kernel(const __half* __restrict__ x,
                      const __half* __restrict__ wq,
                      __half* __restrict__ oh)
{
    extern __shared__ char smem_raw[];
    char* smem = (char*)(((uintptr_t)smem_raw + 1023) & ~(uintptr_t)1023);
    uint32_t sb = smem_u32(smem);

    const int hd  = blockIdx.x;
    const int stripe = blockIdx.y;
    const int tid = threadIdx.x;
    const int lane = tid & 31;
    const int wm = tid >> 5;
    const int rowBase = stripe * 128;

    // bias (mask) — independent of the pipeline
    *(float*)(smem + F_BIAS + tid * 4) = g_mask[rowBase + tid] ? -1e9f : 0.f;

    const int aRow = (lane & 15);
    const int aHalf = (lane >> 4) * 16;
    const int bRow = ((lane >> 4) << 3) + (lane & 7);
    const int bHalf = ((lane >> 3) & 1) * 16;

    // ---- QKV GEMM: acc[mt][nt 0..11], nt: 0-3 q, 4-7 k, 8-11 v ----
    float acc[2][12][4];
    #pragma unroll
    for (int i = 0; i < 2; i++)
        #pragma unroll
        for (int j = 0; j < 12; j++)
            #pragma unroll
            for (int k = 0; k < 4; k++) acc[i][j][k] = 0.f;

    auto load_chunk = [&](int c, int s) {
        int k0 = c * 32;
        uint32_t As = sb + F_ASTAGE + (uint32_t)s * 10240;
        uint32_t Ws = sb + F_WSTAGE + (uint32_t)s * 7680;
        #pragma unroll
        for (int it = 0; it < 4; it++) {
            int idx = it * 128 + tid;
            int row = idx >> 2, seg = idx & 3;
            cpa16(As + (uint32_t)(row * 80 + seg * 16),
                  x + (size_t)(rowBase + row) * 256 + k0 + seg * 8);
        }
        #pragma unroll
        for (int it = 0; it < 3; it++) {
            int idx = it * 128 + tid;
            int wr = idx >> 2, seg = idx & 3;
            int wbase = wr + 32 * hd + (wr >> 5) * 224;   // q/k/v strips of Wqkv
            cpa16(Ws + (uint32_t)(wr * 80 + seg * 16),
                  wq + (size_t)wbase * 256 + k0 + seg * 8);
        }
        CPA_COMMIT();
    };

    load_chunk(0, 0);

    for (int c = 0; c < 8; c++) {
        if (c < 7) { load_chunk(c + 1, (c + 1) & 1); CPA_WAIT1(); }
        else       { CPA_WAIT0(); }
        __syncthreads();

        uint32_t As = sb + F_ASTAGE + (uint32_t)(c & 1) * 10240;
        uint32_t Ws = sb + F_WSTAGE + (uint32_t)(c & 1) * 7680;
        #pragma unroll
        for (int kk = 0; kk < 2; kk++) {
            uint32_t a[2][4];
            #pragma unroll
            for (int mt = 0; mt < 2; mt++)
                LDSM_X4(a[mt], As + (uint32_t)((wm * 32 + mt * 16 + aRow) * 80 + kk * 32 + aHalf));
            #pragma unroll
            for (int p = 0; p < 6; p++) {
                uint32_t bf[4];
                LDSM_X4(bf, Ws + (uint32_t)((p * 16 + bRow) * 80 + kk * 32 + bHalf));
                #pragma unroll
                for (int t2 = 0; t2 < 2; t2++) {
                    int nt = p * 2 + t2;
                    #pragma unroll
                    for (int mt = 0; mt < 2; mt++)
                        mma16816(acc[mt][nt], a[mt], &bf[t2 * 2]);
                }
            }
        }
        __syncthreads();
    }

    // ---- rotary (head 0: all 32 dims of q and k) ----
    if (hd == 0) {
        #pragma unroll
        for (int grp = 0; grp < 2; grp++) {           // 0: q tiles 0-3, 1: k tiles 4-7
            #pragma unroll
            for (int nt4 = 0; nt4 < 4; nt4++) {
                int nt = grp * 4 + nt4;
                int p = nt4 * 4 + (lane & 3);         // rotary pair index 0..15
                float invf = __expf(-(float)(p & 7) * 1.1512925464970228f);
                #pragma unroll
                for (int mt = 0; mt < 2; mt++) {
                    float* cc = acc[mt][nt];
                    #pragma unroll
                    for (int rr = 0; rr < 2; rr++) {
                        int m = rowBase + wm * 32 + mt * 16 + (lane >> 2) + rr * 8;
                        int xx = (m >> 7) & 127;
                        int yy = m & 127;
                        float pos  = (p < 8) ? (float)xx : (float)yy;
                        float tpos = (2.f * pos - 127.f) * (1.f / 127.f);
                        float sn, cs;
                        __sincosf(tpos * invf, &sn, &cs);
                        float e0 = cc[rr * 2], e1 = cc[rr * 2 + 1];
                        cc[rr * 2]     = e0 * cs - e1 * sn;
                        cc[rr * 2 + 1] = e1 * cs + e0 * sn;
                    }
                }
            }
        }
    }

    // ---- Q: scale + pack to A-fragments (C-frag == A-frag identity) ----
    uint32_t aq[2][2][4];
    #pragma unroll
    for (int kk = 0; kk < 2; kk++)
        #pragma unroll
        for (int mt = 0; mt < 2; mt++) {
            const float* t0 = acc[mt][2 * kk];
            const float* t1 = acc[mt][2 * kk + 1];
            aq[kk][mt][0] = packh2(t0[0] * SCALE, t0[1] * SCALE);
            aq[kk][mt][1] = packh2(t0[2] * SCALE, t0[3] * SCALE);
            aq[kk][mt][2] = packh2(t1[0] * SCALE, t1[1] * SCALE);
            aq[kk][mt][3] = packh2(t1[2] * SCALE, t1[3] * SCALE);
        }

    // ---- K, V: C-frags -> 80B-pitch row-layout smem ----
    #pragma unroll
    for (int nt4 = 0; nt4 < 4; nt4++) {
        int dq2 = (nt4 * 8 + 2 * (lane & 3)) * 2;     // byte offset of d within row
        #pragma unroll
        for (int mt = 0; mt < 2; mt++) {
            int row = wm * 32 + mt * 16 + (lane >> 2);
            const float* ck = acc[mt][4 + nt4];
            *(uint32_t*)(smem + F_K + row * 80 + dq2)       = packh2(ck[0], ck[1]);
            *(uint32_t*)(smem + F_K + (row + 8) * 80 + dq2) = packh2(ck[2], ck[3]);
            const float* cv = acc[mt][8 + nt4];
            *(uint32_t*)(smem + F_V + row * 80 + dq2)       = packh2(cv[0], cv[1]);
            *(uint32_t*)(smem + F_V + (row + 8) * 80 + dq2) = packh2(cv[2], cv[3]);
        }
    }
    __syncthreads();

    // ---- S = Q K^T ----
    float sacc[2][16][4];
    #pragma unroll
    for (int i = 0; i < 2; i++)
        #pragma unroll
        for (int j = 0; j < 16; j++)
            #pragma unroll
            for (int k = 0; k < 4; k++) sacc[i][j][k] = 0.f;

    #pragma unroll
    for (int kk = 0; kk < 2; kk++) {
        #pragma unroll
        for (int p = 0; p < 8; p++) {
            uint32_t bo = (uint32_t)((p * 16 + bRow) * 80 + kk * 32 + bHalf);
            uint32_t bf[4];
            LDSM_X4(bf, sb + F_K + bo);
            #pragma unroll
            for (int t2 = 0; t2 < 2; t2++) {
                int nt = p * 2 + t2;
                #pragma unroll
                for (int mt = 0; mt < 2; mt++)
                    mma16816(sacc[mt][nt], aq[kk][mt], &bf[t2 * 2]);
            }
        }
    }

    // ---- softmax (no max-sub) + P fp16 fragments ----
    uint32_t Ph[2][8][4];
    float rsum[2][2];

    #pragma unroll
    for (int mt = 0; mt < 2; mt++) {
        float s0 = 0.f, s1 = 0.f;
        #pragma unroll
        for (int nt = 0; nt < 16; nt++) {
            float2 bb = *(float2*)(smem + F_BIAS + (nt * 8 + 2 * (lane & 3)) * 4);
            float e0 = __expf(sacc[mt][nt][0] + bb.x);
            float e1 = __expf(sacc[mt][nt][1] + bb.y);
            float e2 = __expf(sacc[mt][nt][2] + bb.x);
            float e3 = __expf(sacc[mt][nt][3] + bb.y);
            sacc[mt][nt][0] = e0; sacc[mt][nt][1] = e1;
            sacc[mt][nt][2] = e2; sacc[mt][nt][3] = e3;
            s0 += e0 + e1; s1 += e2 + e3;
        }
        s0 += __shfl_xor_sync(0xffffffffu, s0, 1);
        s0 += __shfl_xor_sync(0xffffffffu, s0, 2);
        s1 += __shfl_xor_sync(0xffffffffu, s1, 1);
        s1 += __shfl_xor_sync(0xffffffffu, s1, 2);
        rsum[mt][0] = s0; rsum[mt][1] = s1;

        #pragma unroll
        for (int kt = 0; kt < 8; kt++) {
            #pragma unroll
            for (int half = 0; half < 2; half++) {
                const float* c = sacc[mt][2 * kt + half];
                Ph[mt][kt][half * 2 + 0] = packh2(c[0], c[1]);
                Ph[mt][kt][half * 2 + 1] = packh2(c[2], c[3]);
            }
        }
    }

    // ---- O = P V via ldmatrix.trans on row-layout V ----
    float pacc[2][4][4];
    #pragma unroll
    for (int i = 0; i < 2; i++)
        #pragma unroll
        for (int j = 0; j < 4; j++)
            #pragma unroll
            for (int k = 0; k < 4; k++) pacc[i][j][k] = 0.f;

    const int vjOff = ((lane >> 3) & 1) * 8 + (lane & 7);
    const int vdOff = ((lane >> 4) & 1) * 16;

    #pragma unroll
    for (int kt = 0; kt < 8; kt++) {
        #pragma unroll
        for (int p2 = 0; p2 < 2; p2++) {
            uint32_t vo = (uint32_t)((kt * 16 + vjOff) * 80 + p2 * 32 + vdOff);
            uint32_t vf[4];
            LDSM_X4_T(vf, sb + F_V + vo);
            #pragma unroll
            for (int t2 = 0; t2 < 2; t2++) {
                int nt = p2 * 2 + t2;
                #pragma unroll
                for (int mt = 0; mt < 2; mt++)
                    mma16816(pacc[mt][nt], Ph[mt][kt], &vf[t2 * 2]);
            }
        }
    }

    // ---- epilogue: divide by row sum, fp16 store to g_att ----
    #pragma unroll
    for (int mt = 0; mt < 2; mt++) {
        float r0 = 1.f / rsum[mt][0];
        float r1 = 1.f / rsum[mt][1];
        int row0 = rowBase + wm * 32 + mt * 16 + (lane >> 2);
        #pragma unroll
        for (int nt = 0; nt < 4; nt++) {
            int col = hd * HD + nt * 8 + 2 * (lane & 3);
            size_t base0 = (size_t)row0 * DD + col;
            size_t base1 = (size_t)(row0 + 8) * DD + col;
            *(uint32_t*)((char*)oh + base0 * 2) = packh2(pacc[mt][nt][0] * r0, pacc[mt][nt][1] * r0);
            *(uint32_t*)((char*)oh + base1 * 2) = packh2(pacc[mt][nt][2] * r1, pacc[mt][nt][3] * r1);
        }
    }
}

// ===========================================================================
// fp16 single-pass NT GEMM (out-projection), cp.async double-buffered.
// BM=128, BN=128, BK=64; 256 threads; __launch_bounds__(256, 2).
// ===========================================================================
#define OFF_A 0
#define OFF_B 16384
#define STAGE_SZ 32768
#define GEMM_SMEM (2*STAGE_SZ + 1024)

template<int N>
__global__ void __launch_bounds__(256, 2)
gemm_fp16_kernel(const __half* __restrict__ A,
                 const __half* __restrict__ B,
                 float* __restrict__ C)
{
    extern __shared__ char smem_raw[];
    char* smem = (char*)(((uintptr_t)smem_raw + 1023) & ~(uintptr_t)1023);
    uint32_t sb = smem_u32(smem);

    const int tid = threadIdx.x;
    const int lane = tid & 31;
    const int wid = tid >> 5;
    const int wm = wid & 3;
    const int wn = wid >> 2;
    const int m0 = blockIdx.y * 128;
    const int n0 = blockIdx.x * 128;

    float acc[2][8][4];
    #pragma unroll
    for (int i = 0; i < 2; i++)
        #pragma unroll
        for (int j = 0; j < 8; j++)
            #pragma unroll
            for (int k = 0; k < 4; k++) acc[i][j][k] = 0.f;

    const int aRow = (lane & 15);
    const int aHalf = (lane >> 4) * 16;
    const int bRow = ((lane >> 4) << 3) + (lane & 7);
    const int bHalf = ((lane >> 3) & 1) * 16;

    const int ldRow = tid >> 3;
    const int ldCs  = tid & 7;

    auto load_chunk = [&](int chunk, int buf) {
        int k0 = chunk * 64;
        uint32_t stage = sb + (uint32_t)buf * STAGE_SZ;
        #pragma unroll
        for (int s = 0; s < 4; s++) {
            int row = s * 32 + ldRow;
            uint32_t so = swz((uint32_t)(row * 128 + ldCs * 16));
            cpa16(stage + OFF_A + so, A + (size_t)(m0 + row) * 256 + k0 + ldCs * 8);
            cpa16(stage + OFF_B + so, B + (size_t)(n0 + row) * 256 + k0 + ldCs * 8);
        }
        CPA_COMMIT();
    };

    load_chunk(0, 0);

    for (int chunk = 0; chunk < 4; chunk++) {
        if (chunk < 3) {
            load_chunk(chunk + 1, (chunk + 1) & 1);
            CPA_WAIT1();
        } else {
            CPA_WAIT0();
        }
        __syncthreads();

        uint32_t stage = sb + (uint32_t)(chunk & 1) * STAGE_SZ;
        #pragma unroll
        for (int kk = 0; kk < 4; kk++) {
            int kb = kk * 32;
            uint32_t a[2][4];
            #pragma unroll
            for (int mt = 0; mt < 2; mt++) {
                uint32_t o = swz((uint32_t)((wm * 32 + mt * 16 + aRow) * 128 + kb + aHalf));
                LDSM_X4(a[mt], stage + OFF_A + o);
            }
            #pragma unroll
            for (int p = 0; p < 4; p++) {
                uint32_t bo = swz((uint32_t)((wn * 64 + p * 16 + bRow) * 128 + kb + bHalf));
                uint32_t bf[4];
                LDSM_X4(bf, stage + OFF_B + bo);
                #pragma unroll
                for (int t2 = 0; t2 < 2; t2++) {
                    int nt = p * 2 + t2;
                    #pragma unroll
                    for (int mt = 0; mt < 2; mt++)
                        mma16816(acc[mt][nt], a[mt], &bf[t2 * 2]);
                }
            }
        }
        __syncthreads();
    }

    #pragma unroll
    for (int mt = 0; mt < 2; mt++) {
        int row0 = m0 + wm * 32 + mt * 16 + (lane >> 2);
        #pragma unroll
        for (int nt = 0; nt < 8; nt++) {
            int colg = n0 + wn * 64 + nt * 8 + (lane & 3) * 2;
            *(float2*)&C[(size_t)row0 * N + colg]       = make_float2(acc[mt][nt][0], acc[mt][nt][1]);
            *(float2*)&C[(size_t)(row0 + 8) * N + colg] = make_float2(acc[mt][nt][2], acc[mt][nt][3]);
        }
    }
}

// ===========================================================================
extern "C" void kernel_launch(void* const* d_in, const int* in_sizes, int n_in,
                              void* d_out, int out_size)
{
    const float* pair_act = nullptr;
    const unsigned char* pair_mask = nullptr;
    const float* ln_gamma = nullptr;
    const float* ln_beta  = nullptr;
    const float* Wqkv = nullptr;
    const float* Wout = nullptr;

    for (int i = 0; i < n_in; i++) {
        int sz = in_sizes[i];
        if      (sz == 8388608) pair_act  = (const float*)d_in[i];
        else if (sz == 32768)   pair_mask = (const unsigned char*)d_in[i];
        else if (sz == 196608)  Wqkv      = (const float*)d_in[i];
        else if (sz == 65536)   Wout      = (const float*)d_in[i];
        else if (sz == 256) {
            if (!ln_gamma) ln_gamma = (const float*)d_in[i];
            else           ln_beta  = (const float*)d_in[i];
        }
    }

    float* out = (float*)d_out;

    void *px, *pat, *pwq, *pwo;
    cudaGetSymbolAddress(&px,  g_x);
    cudaGetSymbolAddress(&pat, g_att);
    cudaGetSymbolAddress(&pwq, g_wq);
    cudaGetSymbolAddress(&pwo, g_wo);

    cudaFuncSetAttribute(fused_qkv_attn_kernel,
                         cudaFuncAttributeMaxDynamicSharedMemorySize, F_SMEM);
    cudaFuncSetAttribute(gemm_fp16_kernel<DD>,
                         cudaFuncAttributeMaxDynamicSharedMemorySize, GEMM_SMEM);

    // Launch order: 4th launch (index 3, the ncu capture target) = fused.
    convw_kernel<<<(QKVN * DD + DD * DD + 255) / 256, 256>>>(
        Wqkv, Wout, (__half*)pwq, (__half*)pwo);                        // 0

    mask_kernel<<<128, 256>>>(pair_mask);                               // 1

    ln_kernel<<<MTOT / 8, 256>>>(pair_act, ln_gamma, ln_beta, (__half*)px);  // 2

    fused_qkv_attn_kernel<<<dim3(NH, MTOT / 128), 128, F_SMEM>>>(
        (const __half*)px, (const __half*)pwq, (__half*)pat);           // 3  <- profiled

    gemm_fp16_kernel<DD><<<dim3(DD / 128, MTOT / 128), 256, GEMM_SMEM>>>(
        (const __half*)pat, (const __half*)pwo, out);                   // 4
}